// round 2
// baseline (speedup 1.0000x reference)
#include <cuda_runtime.h>
#include <cstdint>

constexpr int B_ = 8;     // batch
constexpr int Q_ = 128;   // queries
constexpr int K_ = 1024;  // keys
constexpr int D_ = 512;   // qk feature dim
constexpr int H_ = 256;   // hidden
constexpr int V_ = 512;   // value dim
constexpr int MK = B_ * K_;   // 8192 rows of kproj

// Scratch (no cudaMalloc allowed)
__device__ float g_qproj [B_ * Q_ * H_];   // [B*Q][H]   1 MB
__device__ float g_kprojT[H_ * B_ * K_];   // [H][B*K]   8 MB (transposed)

__device__ __forceinline__ float tanh_fast(float x) {
    float y;
    asm("tanh.approx.f32 %0, %1;" : "=f"(y) : "f"(x));
    return y;
}
__device__ __forceinline__ unsigned long long pack2(float lo, float hi) {
    unsigned long long r;
    asm("mov.b64 %0, {%1, %2};" : "=l"(r) : "f"(lo), "f"(hi));
    return r;
}
__device__ __forceinline__ float2 unpack2(unsigned long long v) {
    float2 r;
    asm("mov.b64 {%0, %1}, %2;" : "=f"(r.x), "=f"(r.y) : "l"(v));
    return r;
}
__device__ __forceinline__ unsigned long long fma2(unsigned long long a,
                                                   unsigned long long b,
                                                   unsigned long long c) {
    unsigned long long d;
    asm("fma.rn.f32x2 %0, %1, %2, %3;" : "=l"(d) : "l"(a), "l"(b), "l"(c));
    return d;
}

// ----------------------------------------------------------------------------
// Merged projection GEMM.
//   blockIdx.y <  16 : qproj tile  -> g_qproj  [B*Q=1024][H] (normal layout)
//   blockIdx.y >= 16 : kproj tile  -> g_kprojT [H][B*K=8192] (transposed)
// 64x64 tile, BK=16, 128 threads, 8x4 microtile, f32x2 packed FMA.
// ----------------------------------------------------------------------------
__global__ __launch_bounds__(128)
void proj_gemm(const float* __restrict__ queries, const float* __restrict__ keys,
               const float* __restrict__ Wq, const float* __restrict__ Wk)
{
    __shared__ float As[16][68];   // A tile transposed: As[k][m]
    __shared__ float Bs[16][64];

    const int tid = threadIdx.x;
    const bool isQ = (blockIdx.y < 16);
    const float* A;
    const float* W;
    long long row0;
    if (isQ) { A = queries; W = Wq; row0 = (long long)blockIdx.y * 64; }
    else     { A = keys;    W = Wk; row0 = (long long)(blockIdx.y - 16) * 64; }
    const int col0 = blockIdx.x * 64;

    const int r0 = (tid >> 4) * 8;     // 8 rows
    const int tn = (tid & 15) * 4;     // 4 cols (as 2 f32x2 pairs)

    unsigned long long acc[8][2];
    #pragma unroll
    for (int i = 0; i < 8; i++) { acc[i][0] = 0ull; acc[i][1] = 0ull; }

    const int l0 = tid * 2;
    for (int kb = 0; kb < D_; kb += 16) {
        #pragma unroll
        for (int u = 0; u < 2; u++) {
            int l = l0 + u;
            // A tile: 64 rows x 16 cols = 256 float4
            int arow = l >> 2, ac4 = (l & 3) * 4;
            float4 av = *(const float4*)(A + (row0 + arow) * D_ + kb + ac4);
            As[ac4 + 0][arow] = av.x;
            As[ac4 + 1][arow] = av.y;
            As[ac4 + 2][arow] = av.z;
            As[ac4 + 3][arow] = av.w;
            // B tile: 16 rows x 64 cols = 256 float4
            int brow = l >> 4, bc4 = (l & 15) * 4;
            *(float4*)&Bs[brow][bc4] =
                *(const float4*)(W + (long long)(kb + brow) * H_ + col0 + bc4);
        }
        __syncthreads();

        #pragma unroll
        for (int kk = 0; kk < 16; kk++) {
            float4 alo = *(const float4*)&As[kk][r0];
            float4 ahi = *(const float4*)&As[kk][r0 + 4];
            float4 bq  = *(const float4*)&Bs[kk][tn];
            unsigned long long b01 = pack2(bq.x, bq.y);
            unsigned long long b23 = pack2(bq.z, bq.w);
            float a[8] = {alo.x, alo.y, alo.z, alo.w, ahi.x, ahi.y, ahi.z, ahi.w};
            #pragma unroll
            for (int ii = 0; ii < 8; ii++) {
                unsigned long long a2 = pack2(a[ii], a[ii]);
                acc[ii][0] = fma2(a2, b01, acc[ii][0]);
                acc[ii][1] = fma2(a2, b23, acc[ii][1]);
            }
        }
        __syncthreads();
    }

    if (isQ) {
        // normal layout: g_qproj[m][n]
        #pragma unroll
        for (int ii = 0; ii < 8; ii++) {
            float2 lo = unpack2(acc[ii][0]);
            float2 hi = unpack2(acc[ii][1]);
            float4 o = make_float4(lo.x, lo.y, hi.x, hi.y);
            *(float4*)(g_qproj + (row0 + r0 + ii) * H_ + col0 + tn) = o;
        }
    } else {
        // transposed: g_kprojT[n][m], m contiguous -> float4 along rows ii
        float vals[8][4];
        #pragma unroll
        for (int ii = 0; ii < 8; ii++) {
            float2 lo = unpack2(acc[ii][0]);
            float2 hi = unpack2(acc[ii][1]);
            vals[ii][0] = lo.x; vals[ii][1] = lo.y;
            vals[ii][2] = hi.x; vals[ii][3] = hi.y;
        }
        #pragma unroll
        for (int jj = 0; jj < 4; jj++) {
            long long n = col0 + tn + jj;
            float4 o0 = make_float4(vals[0][jj], vals[1][jj], vals[2][jj], vals[3][jj]);
            float4 o1 = make_float4(vals[4][jj], vals[5][jj], vals[6][jj], vals[7][jj]);
            *(float4*)(g_kprojT + n * MK + row0 + r0)     = o0;
            *(float4*)(g_kprojT + n * MK + row0 + r0 + 4) = o1;
        }
    }
}

// ----------------------------------------------------------------------------
// Fused: masked tanh-scores + softmax + attn@values.
// Block = (b, q-tile of 4). 256 threads. Lane owns a k (coalesced via kprojT),
// loops h. Scores for k >= vlen are never computed (mask skips them).
// AV loop bounded by vlen; softmax normalization folded into output scale.
// ----------------------------------------------------------------------------
__global__ __launch_bounds__(256)
void fused_attn(const float* __restrict__ wv, const int* __restrict__ vlens,
                const float* __restrict__ values, float* __restrict__ out)
{
    constexpr int QT = 4;
    __shared__ float s_q[QT][H_];    // 4 KB
    __shared__ float s_wv[H_];       // 1 KB
    __shared__ float s_sc[QT][K_];   // 16 KB
    __shared__ float s_red[8];

    const int b   = blockIdx.y;
    const int q0  = blockIdx.x * QT;
    const int tid = threadIdx.x;
    const int lane = tid & 31;
    const int wid  = tid >> 5;
    const int vlen = vlens[b];

    // stage q rows + wv
    for (int i = tid; i < QT * H_; i += 256)
        s_q[i >> 8][i & 255] = g_qproj[(long long)(b * Q_ + q0 + (i >> 8)) * H_ + (i & 255)];
    for (int i = tid; i < H_; i += 256) s_wv[i] = wv[i];
    __syncthreads();

    // ---- scores (masked) ----
    for (int pass = 0; pass < K_ / 256; pass++) {
        int k = pass * 256 + wid * 32 + lane;
        if (k < vlen) {
            const float* kp = g_kprojT + (long long)b * K_ + k;   // + h*MK
            float a0 = 0.f, a1 = 0.f, a2 = 0.f, a3 = 0.f;
            #pragma unroll 4
            for (int h = 0; h < H_; h++) {
                float kv = kp[(long long)h * MK];
                float w  = s_wv[h];
                a0 = fmaf(tanh_fast(s_q[0][h] + kv), w, a0);
                a1 = fmaf(tanh_fast(s_q[1][h] + kv), w, a1);
                a2 = fmaf(tanh_fast(s_q[2][h] + kv), w, a2);
                a3 = fmaf(tanh_fast(s_q[3][h] + kv), w, a3);
            }
            s_sc[0][k] = a0; s_sc[1][k] = a1; s_sc[2][k] = a2; s_sc[3][k] = a3;
        }
    }
    __syncthreads();

    // ---- masked softmax (unnormalized exp in smem, inv kept in regs) ----
    float inv[QT];
    for (int j = 0; j < QT; j++) {
        float m = -3.4e38f;
        for (int k = tid; k < vlen; k += 256) m = fmaxf(m, s_sc[j][k]);
        #pragma unroll
        for (int off = 16; off; off >>= 1)
            m = fmaxf(m, __shfl_xor_sync(0xffffffffu, m, off));
        if (lane == 0) s_red[wid] = m;
        __syncthreads();
        float mm = s_red[0];
        #pragma unroll
        for (int w = 1; w < 8; w++) mm = fmaxf(mm, s_red[w]);
        __syncthreads();

        float s = 0.f;
        for (int k = tid; k < vlen; k += 256) {
            float e = __expf(s_sc[j][k] - mm);
            s_sc[j][k] = e;
            s += e;
        }
        #pragma unroll
        for (int off = 16; off; off >>= 1)
            s += __shfl_xor_sync(0xffffffffu, s, off);
        if (lane == 0) s_red[wid] = s;
        __syncthreads();
        float ssum = 0.f;
        #pragma unroll
        for (int w = 0; w < 8; w++) ssum += s_red[w];
        inv[j] = 1.0f / ssum;
        __syncthreads();
    }

    // ---- AV: out[j][v] = inv[j] * sum_{k<vlen} e[j][k] * values[b][k][v] ----
    const int v0 = tid * 2;
    const float* vb = values + (long long)b * K_ * V_ + v0;
    unsigned long long acc[QT] = {0ull, 0ull, 0ull, 0ull};
    int k = 0;
    #pragma unroll 1
    for (; k + 2 <= vlen; k += 2) {
        float2 vv0 = *(const float2*)(vb + (long long)k * V_);
        float2 vv1 = *(const float2*)(vb + (long long)(k + 1) * V_);
        unsigned long long p0 = pack2(vv0.x, vv0.y);
        unsigned long long p1 = pack2(vv1.x, vv1.y);
        #pragma unroll
        for (int j = 0; j < QT; j++) {
            float e0 = s_sc[j][k];
            float e1 = s_sc[j][k + 1];
            acc[j] = fma2(pack2(e0, e0), p0, acc[j]);
            acc[j] = fma2(pack2(e1, e1), p1, acc[j]);
        }
    }
    if (k < vlen) {
        float2 vv = *(const float2*)(vb + (long long)k * V_);
        unsigned long long p = pack2(vv.x, vv.y);
        #pragma unroll
        for (int j = 0; j < QT; j++) {
            float e = s_sc[j][k];
            acc[j] = fma2(pack2(e, e), p, acc[j]);
        }
    }
    #pragma unroll
    for (int j = 0; j < QT; j++) {
        float2 r = unpack2(acc[j]);
        float2 o = make_float2(r.x * inv[j], r.y * inv[j]);
        *(float2*)(out + (long long)(b * Q_ + q0 + j) * V_ + v0) = o;
    }
}

// ----------------------------------------------------------------------------
extern "C" void kernel_launch(void* const* d_in, const int* in_sizes, int n_in,
                              void* d_out, int out_size)
{
    const float* queries = (const float*)d_in[0];  // [B,Q,D]
    const float* keys    = (const float*)d_in[1];  // [B,K,D]
    const float* values  = (const float*)d_in[2];  // [B,K,V]
    const int*   vlens   = (const int*)  d_in[3];  // [B]
    const float* Wq      = (const float*)d_in[4];  // [D,H]
    const float* Wk      = (const float*)d_in[5];  // [D,H]
    const float* wv      = (const float*)d_in[6];  // [H]
    float* out = (float*)d_out;                    // [B,Q,V]

    // merged projections: 16 qproj row-tiles + 128 kproj row-tiles
    proj_gemm<<<dim3(H_ / 64, 16 + 128), 128>>>(queries, keys, Wq, Wk);

    // fused masked scores + softmax + AV
    fused_attn<<<dim3(Q_ / 4, B_), 256>>>(wv, vlens, values, out);
}